// round 4
// baseline (speedup 1.0000x reference)
#include <cuda_runtime.h>
#include <math_constants.h>
#include <cstdint>

#define NNODES 65536
#define NEDGES 1048576
#define NGRAPH 64
#define NPER   1024
#define FEAT   64
#define HID    128
#define TOPK   10

// ---------------- device scratch (no allocations allowed) ----------------
__device__ int      g_deg[NNODES];
__device__ float    g_dinv[NNODES];
__device__ int      g_off[NNODES];
__device__ int      g_cursor[NNODES];
__device__ uint32_t g_offdeg[NNODES];   // off | (deg << 21)
__device__ int      g_bsum[256];
__device__ float2   g_csre[NEDGES];     // {bits(src_local), norm}
__device__ float    g_c[NNODES];
__device__ float    g_T0[NNODES * HID];
__device__ float    g_T1[NNODES * HID];
__device__ float    g_T2[NNODES * HID];
__device__ float    g_mpp[NGRAPH * 8 * HID];
__device__ float    g_mp[NGRAPH * HID];
__device__ float    g_gW[NGRAPH * HID];
__device__ float    g_z[NNODES];

// ---------------- tf32 helpers ----------------
__device__ __forceinline__ void split_tf32(float a, uint32_t& hi, uint32_t& lo) {
    asm("cvt.rna.tf32.f32 %0, %1;" : "=r"(hi) : "f"(a));
    float r = a - __uint_as_float(hi);
    asm("cvt.rna.tf32.f32 %0, %1;" : "=r"(lo) : "f"(r));
}

__device__ __forceinline__ void mma_tf32(float4& d, const uint32_t a[4], const uint32_t b[2]) {
    asm volatile(
        "mma.sync.aligned.m16n8k8.row.col.f32.tf32.tf32.f32 "
        "{%0,%1,%2,%3}, {%4,%5,%6,%7}, {%8,%9}, {%0,%1,%2,%3};"
        : "+f"(d.x), "+f"(d.y), "+f"(d.z), "+f"(d.w)
        : "r"(a[0]), "r"(a[1]), "r"(a[2]), "r"(a[3]), "r"(b[0]), "r"(b[1]));
}

// ---------------- CSR construction ----------------
__global__ void k_hist(const int* __restrict__ edst) {
    int e = blockIdx.x * 256 + threadIdx.x;
    if (e < NEDGES) atomicAdd(&g_deg[edst[e]], 1);
}

__global__ void k_scan1() {
    __shared__ int s[256];
    int t = threadIdx.x;
    int i = blockIdx.x * 256 + t;
    int v = g_deg[i];
    g_dinv[i] = rsqrtf((float)(v + 1));
    s[t] = v;
    __syncthreads();
    for (int off = 1; off < 256; off <<= 1) {
        int x = s[t];
        if (t >= off) x += s[t - off];
        __syncthreads();
        s[t] = x;
        __syncthreads();
    }
    g_off[i] = s[t] - v;
    if (t == 255) g_bsum[blockIdx.x] = s[t];
}

__global__ void k_scan2() {
    __shared__ int s[256];
    int t = threadIdx.x;
    int v = g_bsum[t];
    s[t] = v;
    __syncthreads();
    for (int off = 1; off < 256; off <<= 1) {
        int x = s[t];
        if (t >= off) x += s[t - off];
        __syncthreads();
        s[t] = x;
        __syncthreads();
    }
    g_bsum[t] = s[t] - v;   // exclusive
}

__global__ void k_scan3() {
    int i = blockIdx.x * 256 + threadIdx.x;
    int o = g_off[i] + g_bsum[blockIdx.x];
    g_off[i] = o;
    g_cursor[i] = o;
    g_offdeg[i] = (uint32_t)o | ((uint32_t)g_deg[i] << 21);
}

__global__ void k_fill(const int* __restrict__ esrc, const int* __restrict__ edst) {
    int e = blockIdx.x * 256 + threadIdx.x;
    if (e >= NEDGES) return;
    int s = esrc[e], d = edst[e];
    float nr = g_dinv[s] * g_dinv[d];
    int slot = atomicAdd(&g_cursor[d], 1);
    g_csre[slot] = make_float2(__int_as_float(s & (NPER - 1)), nr);
}

// ---------------- smem-resident aggregation ----------------
// One block per (graph, 32-feature slice). Stages the slice (128KB) in smem,
// gathers neighbors from smem. WRITE_C: also emit c[n] = sum of incoming norms.
template <int K, bool WRITE_C>
__global__ __launch_bounds__(512) void k_sagg(const float* __restrict__ X,
                                              float* __restrict__ Y) {
    extern __shared__ float sX[];   // NPER * 32 floats = 128KB
    const int S = K / 32;
    const int g = blockIdx.x / S, q = blockIdx.x % S;
    const int base = g * NPER;
    const int tid = threadIdx.x;

    for (int i = tid; i < NPER * 8; i += 512) {
        int row = i >> 3, c = i & 7;
        float4 v = *(const float4*)&X[(size_t)(base + row) * K + q * 32 + c * 4];
        *(float4*)&sX[row * 32 + c * 4] = v;
    }
    __syncthreads();

    const int lane = tid & 31, w = tid >> 5;   // 16 warps
    for (int ln = w; ln < NPER; ln += 16) {
        int node = base + ln;
        uint32_t od = g_offdeg[node];
        int off = od & 0x1FFFFF, deg = od >> 21;
        float dv = g_dinv[node];
        float sl = dv * dv;
        float acc = sl * sX[ln * 32 + lane];
        float csum = sl;
        const float2* ep = &g_csre[off];
        #pragma unroll 4
        for (int j = 0; j < deg; j++) {
            float2 e = ep[j];                    // uniform LDG.64 (broadcast)
            int s = __float_as_int(e.x);
            acc += e.y * sX[s * 32 + lane];      // conflict-free LDS
            csum += e.y;
        }
        Y[(size_t)node * K + q * 32 + lane] = acc;
        if (WRITE_C && q == 0 && lane == 0) g_c[node] = csum;
    }
}

// ---------------- 3xTF32 mma.sync GEMM: Y[128 rows/blk, 128] ----------------
template <int K, bool RELU, bool GLOB>
__global__ __launch_bounds__(256) void k_mgemm(
    const float* __restrict__ A, const float* __restrict__ W,
    const float* __restrict__ bias, float* __restrict__ Y) {
    extern __shared__ float sm[];
    const int PA = K + 4;
    float* sA = sm;                 // 128 * PA
    float* sB = sm + 128 * PA;      // K * 136
    const int tid = threadIdx.x;
    const int rbase = blockIdx.x * 128;

    for (int i = tid; i < 128 * (K / 4); i += 256) {
        int row = i / (K / 4), c = i % (K / 4);
        float4 v = *(const float4*)&A[(size_t)(rbase + row) * K + c * 4];
        *(float4*)&sA[row * PA + c * 4] = v;
    }
    for (int i = tid; i < K * 32; i += 256) {
        int row = i / 32, c = i % 32;
        *(float4*)&sB[row * 136 + c * 4] = *(const float4*)&W[row * 128 + c * 4];
    }
    __syncthreads();

    const int lane = tid & 31, wid = tid >> 5;
    const int gp = lane >> 2, tg = lane & 3;
    const int m0 = (wid & 3) * 32, n0 = (wid >> 2) * 64;

    float4 acc[2][8];
    #pragma unroll
    for (int mf = 0; mf < 2; mf++)
        #pragma unroll
        for (int f = 0; f < 8; f++) acc[mf][f] = make_float4(0.f, 0.f, 0.f, 0.f);

    for (int ks = 0; ks < K / 8; ks++) {
        const int kc = ks * 8;
        uint32_t ah[2][4], al[2][4];
        #pragma unroll
        for (int mf = 0; mf < 2; mf++) {
            int r0 = m0 + mf * 16 + gp;
            float x0 = sA[r0 * PA + kc + tg];
            float x1 = sA[(r0 + 8) * PA + kc + tg];
            float x2 = sA[r0 * PA + kc + tg + 4];
            float x3 = sA[(r0 + 8) * PA + kc + tg + 4];
            split_tf32(x0, ah[mf][0], al[mf][0]);
            split_tf32(x1, ah[mf][1], al[mf][1]);
            split_tf32(x2, ah[mf][2], al[mf][2]);
            split_tf32(x3, ah[mf][3], al[mf][3]);
        }
        #pragma unroll
        for (int f = 0; f < 8; f++) {
            int n = n0 + f * 8 + gp;
            float y0 = sB[(kc + tg) * 136 + n];
            float y1 = sB[(kc + tg + 4) * 136 + n];
            uint32_t bh[2], bl[2];
            split_tf32(y0, bh[0], bl[0]);
            split_tf32(y1, bh[1], bl[1]);
            #pragma unroll
            for (int mf = 0; mf < 2; mf++) {
                mma_tf32(acc[mf][f], ah[mf], bh);
                mma_tf32(acc[mf][f], ah[mf], bl);
                mma_tf32(acc[mf][f], al[mf], bh);
            }
        }
    }

    const float* gw = GLOB ? &g_gW[(rbase >> 10) * HID] : nullptr;
    #pragma unroll
    for (int mf = 0; mf < 2; mf++) {
        int r0 = rbase + m0 + mf * 16 + gp;
        int r1 = r0 + 8;
        float cc0 = GLOB ? g_c[r0] : 0.f;
        float cc1 = GLOB ? g_c[r1] : 0.f;
        #pragma unroll
        for (int f = 0; f < 8; f++) {
            int c = n0 + f * 8 + 2 * tg;
            float2 bv = *(const float2*)&bias[c];
            float4 a = acc[mf][f];
            float2 o0 = {a.x + bv.x, a.y + bv.y};
            float2 o1 = {a.z + bv.x, a.w + bv.y};
            if (GLOB) {
                float2 gv = *(const float2*)&gw[c];
                o0.x += cc0 * gv.x; o0.y += cc0 * gv.y;
                o1.x += cc1 * gv.x; o1.y += cc1 * gv.y;
            }
            if (RELU) {
                o0.x = fmaxf(o0.x, 0.f); o0.y = fmaxf(o0.y, 0.f);
                o1.x = fmaxf(o1.x, 0.f); o1.y = fmaxf(o1.y, 0.f);
            }
            *(float2*)&Y[(size_t)r0 * 128 + c] = o0;
            *(float2*)&Y[(size_t)r1 * 128 + c] = o1;
        }
    }
}

// ---------------- max pool (two stage) + global path matmuls ----------------
__global__ void k_maxpool1(const float* __restrict__ H) {
    int g = blockIdx.x >> 3, s = blockIdx.x & 7, f = threadIdx.x;
    const float* p = H + ((size_t)g * NPER + s * 128) * HID + f;
    float m = -CUDART_INF_F;
    for (int i = 0; i < 128; i++) m = fmaxf(m, p[(size_t)i * HID]);
    g_mpp[(g * 8 + s) * HID + f] = m;
}

__global__ void k_maxpool2() {
    int g = blockIdx.x, f = threadIdx.x;
    float m = -CUDART_INF_F;
    #pragma unroll
    for (int s = 0; s < 8; s++) m = fmaxf(m, g_mpp[(g * 8 + s) * HID + f]);
    g_mp[g * HID + f] = m;
}

__global__ void k_globs(const float* __restrict__ Wf, const float* __restrict__ bf,
                        const float* __restrict__ W2) {
    __shared__ float s1[HID];
    __shared__ float s2[HID];
    int g = blockIdx.x, t = threadIdx.x;
    s1[t] = g_mp[g * HID + t];
    __syncthreads();
    float acc = bf[t];
    for (int k = 0; k < HID; k++) acc += s1[k] * Wf[k * HID + t];
    s2[t] = acc;
    __syncthreads();
    float a2 = 0.f;
    for (int k = 0; k < HID; k++) a2 += s2[k] * W2[(HID + k) * HID + t];
    g_gW[g * HID + t] = a2;
}

// ---------------- final projection ----------------
__global__ void k_z(const float* __restrict__ H, const float* __restrict__ W3) {
    int node = blockIdx.x * 8 + (threadIdx.x >> 5);
    int lane = threadIdx.x & 31;
    float4 h = ((const float4*)H)[node * 32 + lane];
    float4 w = ((const float4*)W3)[lane];
    float d = h.x * w.x + h.y * w.y + h.z * w.z + h.w * w.w;
    #pragma unroll
    for (int o = 16; o; o >>= 1) d += __shfl_xor_sync(0xffffffffu, d, o);
    if (lane == 0) g_z[node] = d;
}

// ---------------- fused logit + per-graph top-K mask ----------------
__global__ __launch_bounds__(256) void k_logitk(const float* __restrict__ b3,
                                                float* __restrict__ out) {
    __shared__ float sz[NPER];
    __shared__ float slog[NPER];
    __shared__ float v[NPER];
    __shared__ float wmax[8];
    __shared__ float sth;
    __shared__ int sidx;
    const int g = blockIdx.x, t = threadIdx.x;
    const int lane = t & 31, warp = t >> 5;
    const float bb = b3[0];

    for (int i = t; i < NPER; i += 256) sz[i] = g_z[g * NPER + i];
    __syncthreads();

    for (int ln = warp; ln < NPER; ln += 8) {
        uint32_t od = g_offdeg[g * NPER + ln];
        int off = od & 0x1FFFFF, deg = od >> 21;
        float part = 0.f;
        for (int j = lane; j < deg; j += 32) {
            float2 e = g_csre[off + j];
            part += e.y * sz[__float_as_int(e.x)];
        }
        #pragma unroll
        for (int o = 16; o; o >>= 1) part += __shfl_xor_sync(0xffffffffu, part, o);
        if (lane == 0) {
            float dv = g_dinv[g * NPER + ln];
            float lv = part + dv * dv * sz[ln] + bb;
            slog[ln] = lv;
            v[ln] = lv;
        }
    }
    __syncthreads();

    for (int it = 0; it < TOPK; it++) {
        float m = -CUDART_INF_F;
        for (int i = t; i < NPER; i += 256) m = fmaxf(m, v[i]);
        #pragma unroll
        for (int o = 16; o; o >>= 1) m = fmaxf(m, __shfl_xor_sync(0xffffffffu, m, o));
        if (lane == 0) wmax[warp] = m;
        __syncthreads();
        if (t == 0) {
            float mm = wmax[0];
            #pragma unroll
            for (int w = 1; w < 8; w++) mm = fmaxf(mm, wmax[w]);
            sth = mm;
            sidx = 0x7fffffff;
        }
        __syncthreads();
        float mm = sth;
        for (int i = t; i < NPER; i += 256)
            if (v[i] == mm) atomicMin(&sidx, i);
        __syncthreads();
        if (t == 0) v[sidx] = -CUDART_INF_F;
        __syncthreads();
    }
    float th = sth;
    for (int i = t; i < NPER; i += 256)
        out[g * NPER + i] = (slog[i] >= th) ? 1.0f : 0.0f;
}

// ---------------- host launcher ----------------
extern "C" void kernel_launch(void* const* d_in, const int* in_sizes, int n_in,
                              void* d_out, int out_size) {
    const float* x    = (const float*)d_in[0];
    const int*   esrc = (const int*)d_in[1];
    const int*   edst = (const int*)d_in[2];
    const float* W0 = (const float*)d_in[4];
    const float* b0 = (const float*)d_in[5];
    const float* W1 = (const float*)d_in[6];
    const float* b1 = (const float*)d_in[7];
    const float* Wf = (const float*)d_in[8];
    const float* bf = (const float*)d_in[9];
    const float* W2 = (const float*)d_in[10];
    const float* b2 = (const float*)d_in[11];
    const float* W3 = (const float*)d_in[12];
    const float* b3 = (const float*)d_in[13];
    float* out = (float*)d_out;

    float *T0, *T1, *T2;
    int* degp;
    cudaGetSymbolAddress((void**)&T0, g_T0);
    cudaGetSymbolAddress((void**)&T1, g_T1);
    cudaGetSymbolAddress((void**)&T2, g_T2);
    cudaGetSymbolAddress((void**)&degp, g_deg);

    const int SMAGG = NPER * 32 * 4;                 // 131072
    const int SM64  = (128 * 68 + 64 * 136) * 4;     // 69632
    const int SM128 = (128 * 132 + 128 * 136) * 4;   // 137216
    cudaFuncSetAttribute(k_sagg<64, true>,   cudaFuncAttributeMaxDynamicSharedMemorySize, SMAGG);
    cudaFuncSetAttribute(k_sagg<128, false>, cudaFuncAttributeMaxDynamicSharedMemorySize, SMAGG);
    cudaFuncSetAttribute(k_mgemm<64, true, false>,  cudaFuncAttributeMaxDynamicSharedMemorySize, SM64);
    cudaFuncSetAttribute(k_mgemm<128, true, false>, cudaFuncAttributeMaxDynamicSharedMemorySize, SM128);
    cudaFuncSetAttribute(k_mgemm<128, true, true>,  cudaFuncAttributeMaxDynamicSharedMemorySize, SM128);

    // --- CSR + norms (6 steps) ---
    cudaMemsetAsync(degp, 0, NNODES * sizeof(int));
    k_hist<<<NEDGES / 256, 256>>>(edst);
    k_scan1<<<256, 256>>>();
    k_scan2<<<1, 256>>>();
    k_scan3<<<256, 256>>>();
    k_fill<<<NEDGES / 256, 256>>>(esrc, edst);

    // --- conv0: h0 = relu(agg(x) @ W0 + b0) (+ c vector) ---
    k_sagg<64, true><<<NGRAPH * 2, 512, SMAGG>>>(x, T2);
    k_mgemm<64, true, false><<<NNODES / 128, 256, SM64>>>(T2, W0, b0, T0);

    // --- global path ---
    k_maxpool1<<<NGRAPH * 8, HID>>>(T0);
    k_maxpool2<<<NGRAPH, HID>>>();
    k_globs<<<NGRAPH, HID>>>(Wf, bf, W2);

    // --- conv1 (applied twice with same weights) ---
    k_sagg<128, false><<<NGRAPH * 4, 512, SMAGG>>>(T0, T1);
    k_mgemm<128, true, false><<<NNODES / 128, 256, SM128>>>(T1, W1, b1, T2);
    k_sagg<128, false><<<NGRAPH * 4, 512, SMAGG>>>(T2, T1);
    k_mgemm<128, true, false><<<NNODES / 128, 256, SM128>>>(T1, W1, b1, T0);

    // --- conv2 on concat: relu(agg(h) @ W2_top + c_n * gW + b2) ---
    k_sagg<128, false><<<NGRAPH * 4, 512, SMAGG>>>(T0, T1);
    k_mgemm<128, true, true><<<NNODES / 128, 256, SM128>>>(T1, W2, b2, T2);

    // --- conv3 (out=1): z = h @ W3, then fused logit + top-10 mask ---
    k_z<<<NNODES / 8, 256>>>(T2, W3);
    k_logitk<<<NGRAPH, 256>>>(b3, out);
}

// round 5
// speedup vs baseline: 1.5325x; 1.5325x over previous
#include <cuda_runtime.h>
#include <math_constants.h>
#include <cstdint>

#define NNODES 65536
#define NEDGES 1048576
#define NGRAPH 64
#define NPER   1024
#define FEAT   64
#define HID    128
#define TOPK   10

// ---------------- device scratch (no allocations allowed) ----------------
__device__ int      g_deg[NNODES];
__device__ float    g_dinv[NNODES];
__device__ int      g_off[NNODES];
__device__ int      g_cursor[NNODES];
__device__ uint32_t g_offdeg[NNODES];   // off | (deg << 21)
__device__ int      g_bsum[256];
__device__ float2   g_csre[NEDGES];     // {bits(src_local), norm}
__device__ float    g_c[NNODES];
__device__ float    g_T0[NNODES * HID];
__device__ float    g_T1[NNODES * HID];
__device__ float    g_T2[NNODES * HID];
__device__ float    g_mpp[NGRAPH * 8 * HID];
__device__ float    g_mp[NGRAPH * HID];
__device__ float    g_gW[NGRAPH * HID];
__device__ float    g_z[NNODES];

// ---------------- tf32 helpers ----------------
__device__ __forceinline__ void split_tf32(float a, uint32_t& hi, uint32_t& lo) {
    asm("cvt.rna.tf32.f32 %0, %1;" : "=r"(hi) : "f"(a));
    float r = a - __uint_as_float(hi);
    asm("cvt.rna.tf32.f32 %0, %1;" : "=r"(lo) : "f"(r));
}

__device__ __forceinline__ void mma_tf32(float4& d, const uint32_t a[4], const uint32_t b[2]) {
    asm volatile(
        "mma.sync.aligned.m16n8k8.row.col.f32.tf32.tf32.f32 "
        "{%0,%1,%2,%3}, {%4,%5,%6,%7}, {%8,%9}, {%0,%1,%2,%3};"
        : "+f"(d.x), "+f"(d.y), "+f"(d.z), "+f"(d.w)
        : "r"(a[0]), "r"(a[1]), "r"(a[2]), "r"(a[3]), "r"(b[0]), "r"(b[1]));
}

// ---------------- CSR construction ----------------
__global__ void k_hist(const int* __restrict__ edst) {
    int e = blockIdx.x * 256 + threadIdx.x;
    if (e < NEDGES) atomicAdd(&g_deg[edst[e]], 1);
}

__global__ void k_scan1() {
    __shared__ int s[256];
    int t = threadIdx.x;
    int i = blockIdx.x * 256 + t;
    int v = g_deg[i];
    g_dinv[i] = rsqrtf((float)(v + 1));
    s[t] = v;
    __syncthreads();
    for (int off = 1; off < 256; off <<= 1) {
        int x = s[t];
        if (t >= off) x += s[t - off];
        __syncthreads();
        s[t] = x;
        __syncthreads();
    }
    g_off[i] = s[t] - v;
    if (t == 255) g_bsum[blockIdx.x] = s[t];
}

__global__ void k_scan2() {
    __shared__ int s[256];
    int t = threadIdx.x;
    int v = g_bsum[t];
    s[t] = v;
    __syncthreads();
    for (int off = 1; off < 256; off <<= 1) {
        int x = s[t];
        if (t >= off) x += s[t - off];
        __syncthreads();
        s[t] = x;
        __syncthreads();
    }
    g_bsum[t] = s[t] - v;   // exclusive
}

__global__ void k_scan3() {
    int i = blockIdx.x * 256 + threadIdx.x;
    int o = g_off[i] + g_bsum[blockIdx.x];
    g_off[i] = o;
    g_cursor[i] = o;
    g_offdeg[i] = (uint32_t)o | ((uint32_t)g_deg[i] << 21);
}

__global__ void k_fill(const int* __restrict__ esrc, const int* __restrict__ edst) {
    int e = blockIdx.x * 256 + threadIdx.x;
    if (e >= NEDGES) return;
    int s = esrc[e], d = edst[e];
    float nr = g_dinv[s] * g_dinv[d];
    int slot = atomicAdd(&g_cursor[d], 1);
    g_csre[slot] = make_float2(__int_as_float(s & (NPER - 1)), nr);
}

// ---------------- L2-gather aggregation (warp per node, lane-preloaded CSR) --------
// WRITE_C: also emit c[n] = sum of incoming norms (needed once, for conv2 global term).
template <bool WRITE_C>
__global__ __launch_bounds__(256) void k_agg64(const float* __restrict__ X,
                                               float* __restrict__ Y) {
    int node = blockIdx.x * 8 + (threadIdx.x >> 5);
    int lane = threadIdx.x & 31;
    const float2* xs = (const float2*)X;
    uint32_t od = g_offdeg[node];
    int off = od & 0x1FFFFF, deg = od >> 21;
    float dv = g_dinv[node];
    float sl = dv * dv;
    float2 xv = xs[node * 32 + lane];
    float2 acc = {sl * xv.x, sl * xv.y};
    float csum = sl;
    const int gbase = (node & ~(NPER - 1)) * 32;   // graph base in float2 units
    for (int j0 = 0; j0 < deg; j0 += 32) {
        int n = min(32, deg - j0);
        float2 e = (lane < n) ? g_csre[off + j0 + lane] : make_float2(0.f, 0.f);
        for (int j = 0; j < n; j++) {
            int s = __shfl_sync(0xffffffffu, __float_as_int(e.x), j);
            float nr = __shfl_sync(0xffffffffu, e.y, j);
            float2 v = xs[gbase + s * 32 + lane];
            acc.x += nr * v.x;
            acc.y += nr * v.y;
            if (WRITE_C) csum += nr;
        }
    }
    ((float2*)Y)[node * 32 + lane] = acc;
    if (WRITE_C && lane == 0) g_c[node] = csum;
}

__global__ __launch_bounds__(256) void k_agg128(const float* __restrict__ X,
                                                float* __restrict__ Y) {
    int node = blockIdx.x * 8 + (threadIdx.x >> 5);
    int lane = threadIdx.x & 31;
    const float4* xs = (const float4*)X;
    uint32_t od = g_offdeg[node];
    int off = od & 0x1FFFFF, deg = od >> 21;
    float dv = g_dinv[node];
    float sl = dv * dv;
    float4 xv = xs[node * 32 + lane];
    float4 acc = {sl * xv.x, sl * xv.y, sl * xv.z, sl * xv.w};
    const int gbase = (node & ~(NPER - 1)) * 32;   // graph base in float4 units
    for (int j0 = 0; j0 < deg; j0 += 32) {
        int n = min(32, deg - j0);
        float2 e = (lane < n) ? g_csre[off + j0 + lane] : make_float2(0.f, 0.f);
        for (int j = 0; j < n; j++) {
            int s = __shfl_sync(0xffffffffu, __float_as_int(e.x), j);
            float nr = __shfl_sync(0xffffffffu, e.y, j);
            float4 v = xs[gbase + s * 32 + lane];
            acc.x += nr * v.x; acc.y += nr * v.y; acc.z += nr * v.z; acc.w += nr * v.w;
        }
    }
    ((float4*)Y)[node * 32 + lane] = acc;
}

// ---------------- 3xTF32 mma.sync GEMM: Y[128 rows/blk, 128] ----------------
template <int K, bool RELU, bool GLOB>
__global__ __launch_bounds__(256) void k_mgemm(
    const float* __restrict__ A, const float* __restrict__ W,
    const float* __restrict__ bias, float* __restrict__ Y) {
    extern __shared__ float sm[];
    const int PA = K + 4;
    float* sA = sm;                 // 128 * PA
    float* sB = sm + 128 * PA;      // K * 136
    const int tid = threadIdx.x;
    const int rbase = blockIdx.x * 128;

    for (int i = tid; i < 128 * (K / 4); i += 256) {
        int row = i / (K / 4), c = i % (K / 4);
        float4 v = *(const float4*)&A[(size_t)(rbase + row) * K + c * 4];
        *(float4*)&sA[row * PA + c * 4] = v;
    }
    for (int i = tid; i < K * 32; i += 256) {
        int row = i / 32, c = i % 32;
        *(float4*)&sB[row * 136 + c * 4] = *(const float4*)&W[row * 128 + c * 4];
    }
    __syncthreads();

    const int lane = tid & 31, wid = tid >> 5;
    const int gp = lane >> 2, tg = lane & 3;
    const int m0 = (wid & 3) * 32, n0 = (wid >> 2) * 64;

    float4 acc[2][8];
    #pragma unroll
    for (int mf = 0; mf < 2; mf++)
        #pragma unroll
        for (int f = 0; f < 8; f++) acc[mf][f] = make_float4(0.f, 0.f, 0.f, 0.f);

    for (int ks = 0; ks < K / 8; ks++) {
        const int kc = ks * 8;
        uint32_t ah[2][4], al[2][4];
        #pragma unroll
        for (int mf = 0; mf < 2; mf++) {
            int r0 = m0 + mf * 16 + gp;
            float x0 = sA[r0 * PA + kc + tg];
            float x1 = sA[(r0 + 8) * PA + kc + tg];
            float x2 = sA[r0 * PA + kc + tg + 4];
            float x3 = sA[(r0 + 8) * PA + kc + tg + 4];
            split_tf32(x0, ah[mf][0], al[mf][0]);
            split_tf32(x1, ah[mf][1], al[mf][1]);
            split_tf32(x2, ah[mf][2], al[mf][2]);
            split_tf32(x3, ah[mf][3], al[mf][3]);
        }
        #pragma unroll
        for (int f = 0; f < 8; f++) {
            int n = n0 + f * 8 + gp;
            float y0 = sB[(kc + tg) * 136 + n];
            float y1 = sB[(kc + tg + 4) * 136 + n];
            uint32_t bh[2], bl[2];
            split_tf32(y0, bh[0], bl[0]);
            split_tf32(y1, bh[1], bl[1]);
            #pragma unroll
            for (int mf = 0; mf < 2; mf++) {
                mma_tf32(acc[mf][f], ah[mf], bh);
                mma_tf32(acc[mf][f], ah[mf], bl);
                mma_tf32(acc[mf][f], al[mf], bh);
            }
        }
    }

    const float* gw = GLOB ? &g_gW[(rbase >> 10) * HID] : nullptr;
    #pragma unroll
    for (int mf = 0; mf < 2; mf++) {
        int r0 = rbase + m0 + mf * 16 + gp;
        int r1 = r0 + 8;
        float cc0 = GLOB ? g_c[r0] : 0.f;
        float cc1 = GLOB ? g_c[r1] : 0.f;
        #pragma unroll
        for (int f = 0; f < 8; f++) {
            int c = n0 + f * 8 + 2 * tg;
            float2 bv = *(const float2*)&bias[c];
            float4 a = acc[mf][f];
            float2 o0 = {a.x + bv.x, a.y + bv.y};
            float2 o1 = {a.z + bv.x, a.w + bv.y};
            if (GLOB) {
                float2 gv = *(const float2*)&gw[c];
                o0.x += cc0 * gv.x; o0.y += cc0 * gv.y;
                o1.x += cc1 * gv.x; o1.y += cc1 * gv.y;
            }
            if (RELU) {
                o0.x = fmaxf(o0.x, 0.f); o0.y = fmaxf(o0.y, 0.f);
                o1.x = fmaxf(o1.x, 0.f); o1.y = fmaxf(o1.y, 0.f);
            }
            *(float2*)&Y[(size_t)r0 * 128 + c] = o0;
            *(float2*)&Y[(size_t)r1 * 128 + c] = o1;
        }
    }
}

// ---------------- max pool (two stage) + global path matmuls ----------------
__global__ void k_maxpool1(const float* __restrict__ H) {
    int g = blockIdx.x >> 3, s = blockIdx.x & 7, f = threadIdx.x;
    const float* p = H + ((size_t)g * NPER + s * 128) * HID + f;
    float m = -CUDART_INF_F;
    for (int i = 0; i < 128; i++) m = fmaxf(m, p[(size_t)i * HID]);
    g_mpp[(g * 8 + s) * HID + f] = m;
}

__global__ void k_maxpool2() {
    int g = blockIdx.x, f = threadIdx.x;
    float m = -CUDART_INF_F;
    #pragma unroll
    for (int s = 0; s < 8; s++) m = fmaxf(m, g_mpp[(g * 8 + s) * HID + f]);
    g_mp[g * HID + f] = m;
}

__global__ void k_globs(const float* __restrict__ Wf, const float* __restrict__ bf,
                        const float* __restrict__ W2) {
    __shared__ float s1[HID];
    __shared__ float s2[HID];
    int g = blockIdx.x, t = threadIdx.x;
    s1[t] = g_mp[g * HID + t];
    __syncthreads();
    float acc = bf[t];
    for (int k = 0; k < HID; k++) acc += s1[k] * Wf[k * HID + t];
    s2[t] = acc;
    __syncthreads();
    float a2 = 0.f;
    for (int k = 0; k < HID; k++) a2 += s2[k] * W2[(HID + k) * HID + t];
    g_gW[g * HID + t] = a2;
}

// ---------------- final projection ----------------
__global__ void k_z(const float* __restrict__ H, const float* __restrict__ W3) {
    int node = blockIdx.x * 8 + (threadIdx.x >> 5);
    int lane = threadIdx.x & 31;
    float4 h = ((const float4*)H)[node * 32 + lane];
    float4 w = ((const float4*)W3)[lane];
    float d = h.x * w.x + h.y * w.y + h.z * w.z + h.w * w.w;
    #pragma unroll
    for (int o = 16; o; o >>= 1) d += __shfl_xor_sync(0xffffffffu, d, o);
    if (lane == 0) g_z[node] = d;
}

// ---------------- fused logit + per-graph top-K mask ----------------
__global__ __launch_bounds__(256) void k_logitk(const float* __restrict__ b3,
                                                float* __restrict__ out) {
    __shared__ float sz[NPER];
    __shared__ float slog[NPER];
    __shared__ float v[NPER];
    __shared__ float wmax[8];
    __shared__ float sth;
    __shared__ int sidx;
    const int g = blockIdx.x, t = threadIdx.x;
    const int lane = t & 31, warp = t >> 5;
    const float bb = b3[0];

    for (int i = t; i < NPER; i += 256) sz[i] = g_z[g * NPER + i];
    __syncthreads();

    for (int ln = warp; ln < NPER; ln += 8) {
        uint32_t od = g_offdeg[g * NPER + ln];
        int off = od & 0x1FFFFF, deg = od >> 21;
        float part = 0.f;
        for (int j = lane; j < deg; j += 32) {
            float2 e = g_csre[off + j];
            part += e.y * sz[__float_as_int(e.x)];
        }
        #pragma unroll
        for (int o = 16; o; o >>= 1) part += __shfl_xor_sync(0xffffffffu, part, o);
        if (lane == 0) {
            float dv = g_dinv[g * NPER + ln];
            float lv = part + dv * dv * sz[ln] + bb;
            slog[ln] = lv;
            v[ln] = lv;
        }
    }
    __syncthreads();

    for (int it = 0; it < TOPK; it++) {
        float m = -CUDART_INF_F;
        for (int i = t; i < NPER; i += 256) m = fmaxf(m, v[i]);
        #pragma unroll
        for (int o = 16; o; o >>= 1) m = fmaxf(m, __shfl_xor_sync(0xffffffffu, m, o));
        if (lane == 0) wmax[warp] = m;
        __syncthreads();
        if (t == 0) {
            float mm = wmax[0];
            #pragma unroll
            for (int w = 1; w < 8; w++) mm = fmaxf(mm, wmax[w]);
            sth = mm;
            sidx = 0x7fffffff;
        }
        __syncthreads();
        float mm = sth;
        for (int i = t; i < NPER; i += 256)
            if (v[i] == mm) atomicMin(&sidx, i);
        __syncthreads();
        if (t == 0) v[sidx] = -CUDART_INF_F;
        __syncthreads();
    }
    float th = sth;
    for (int i = t; i < NPER; i += 256)
        out[g * NPER + i] = (slog[i] >= th) ? 1.0f : 0.0f;
}

// ---------------- host launcher ----------------
extern "C" void kernel_launch(void* const* d_in, const int* in_sizes, int n_in,
                              void* d_out, int out_size) {
    const float* x    = (const float*)d_in[0];
    const int*   esrc = (const int*)d_in[1];
    const int*   edst = (const int*)d_in[2];
    const float* W0 = (const float*)d_in[4];
    const float* b0 = (const float*)d_in[5];
    const float* W1 = (const float*)d_in[6];
    const float* b1 = (const float*)d_in[7];
    const float* Wf = (const float*)d_in[8];
    const float* bf = (const float*)d_in[9];
    const float* W2 = (const float*)d_in[10];
    const float* b2 = (const float*)d_in[11];
    const float* W3 = (const float*)d_in[12];
    const float* b3 = (const float*)d_in[13];
    float* out = (float*)d_out;

    float *T0, *T1, *T2;
    int* degp;
    cudaGetSymbolAddress((void**)&T0, g_T0);
    cudaGetSymbolAddress((void**)&T1, g_T1);
    cudaGetSymbolAddress((void**)&T2, g_T2);
    cudaGetSymbolAddress((void**)&degp, g_deg);

    const int SM64  = (128 * 68 + 64 * 136) * 4;     // 69632
    const int SM128 = (128 * 132 + 128 * 136) * 4;   // 137216
    cudaFuncSetAttribute(k_mgemm<64, true, false>,  cudaFuncAttributeMaxDynamicSharedMemorySize, SM64);
    cudaFuncSetAttribute(k_mgemm<128, true, false>, cudaFuncAttributeMaxDynamicSharedMemorySize, SM128);
    cudaFuncSetAttribute(k_mgemm<128, true, true>,  cudaFuncAttributeMaxDynamicSharedMemorySize, SM128);

    // --- CSR + norms ---
    cudaMemsetAsync(degp, 0, NNODES * sizeof(int));
    k_hist<<<NEDGES / 256, 256>>>(edst);
    k_scan1<<<256, 256>>>();
    k_scan2<<<1, 256>>>();
    k_scan3<<<256, 256>>>();
    k_fill<<<NEDGES / 256, 256>>>(esrc, edst);

    // --- conv0: h0 = relu(agg(x) @ W0 + b0) (+ c vector) ---
    k_agg64<true><<<NNODES / 8, 256>>>(x, T2);
    k_mgemm<64, true, false><<<NNODES / 128, 256, SM64>>>(T2, W0, b0, T0);

    // --- global path ---
    k_maxpool1<<<NGRAPH * 8, HID>>>(T0);
    k_maxpool2<<<NGRAPH, HID>>>();
    k_globs<<<NGRAPH, HID>>>(Wf, bf, W2);

    // --- conv1 (applied twice with same weights) ---
    k_agg128<<<NNODES / 8, 256>>>(T0, T1);
    k_mgemm<128, true, false><<<NNODES / 128, 256, SM128>>>(T1, W1, b1, T2);
    k_agg128<<<NNODES / 8, 256>>>(T2, T1);
    k_mgemm<128, true, false><<<NNODES / 128, 256, SM128>>>(T1, W1, b1, T0);

    // --- conv2 on concat: relu(agg(h) @ W2_top + c_n * gW + b2) ---
    k_agg128<<<NNODES / 8, 256>>>(T0, T1);
    k_mgemm<128, true, true><<<NNODES / 128, 256, SM128>>>(T1, W2, b2, T2);

    // --- conv3 (out=1): z = h @ W3, then fused logit + top-10 mask ---
    k_z<<<NNODES / 8, 256>>>(T2, W3);
    k_logitk<<<NGRAPH, 256>>>(b3, out);
}

// round 6
// speedup vs baseline: 1.5796x; 1.0308x over previous
#include <cuda_runtime.h>
#include <math_constants.h>
#include <cstdint>

#define NNODES 65536
#define NEDGES 1048576
#define NGRAPH 64
#define NPER   1024
#define FEAT   64
#define HID    128
#define TOPK   10

// ---------------- device scratch (no allocations allowed) ----------------
__device__ int      g_deg[NNODES];
__device__ float    g_dinv[NNODES];
__device__ int      g_off[NNODES];
__device__ int      g_cursor[NNODES];
__device__ uint32_t g_offdeg[NNODES];   // off | (deg << 21)
__device__ int      g_bsum[256];
__device__ float2   g_csre[NEDGES];     // {bits(src_local), norm}
__device__ float    g_c[NNODES];
__device__ float    g_T0[NNODES * HID];
__device__ float    g_T1[NNODES * HID];
__device__ float    g_T2[NNODES * HID];
__device__ float    g_mpp[NGRAPH * 8 * HID];
__device__ float    g_mp[NGRAPH * HID];
__device__ float    g_gW[NGRAPH * HID];
__device__ float    g_z[NNODES];

// ---------------- tf32 helpers ----------------
__device__ __forceinline__ void split_tf32(float a, uint32_t& hi, uint32_t& lo) {
    asm("cvt.rna.tf32.f32 %0, %1;" : "=r"(hi) : "f"(a));
    float r = a - __uint_as_float(hi);
    asm("cvt.rna.tf32.f32 %0, %1;" : "=r"(lo) : "f"(r));
}

__device__ __forceinline__ void mma_tf32(float4& d, const uint32_t a[4], const uint32_t b[2]) {
    asm volatile(
        "mma.sync.aligned.m16n8k8.row.col.f32.tf32.tf32.f32 "
        "{%0,%1,%2,%3}, {%4,%5,%6,%7}, {%8,%9}, {%0,%1,%2,%3};"
        : "+f"(d.x), "+f"(d.y), "+f"(d.z), "+f"(d.w)
        : "r"(a[0]), "r"(a[1]), "r"(a[2]), "r"(a[3]), "r"(b[0]), "r"(b[1]));
}

// ---------------- CSR construction ----------------
__global__ void k_hist(const int* __restrict__ edst) {
    int e = blockIdx.x * 256 + threadIdx.x;
    if (e < NEDGES) atomicAdd(&g_deg[edst[e]], 1);
}

__global__ void k_scan1() {
    __shared__ int s[256];
    int t = threadIdx.x;
    int i = blockIdx.x * 256 + t;
    int v = g_deg[i];
    g_dinv[i] = rsqrtf((float)(v + 1));
    s[t] = v;
    __syncthreads();
    for (int off = 1; off < 256; off <<= 1) {
        int x = s[t];
        if (t >= off) x += s[t - off];
        __syncthreads();
        s[t] = x;
        __syncthreads();
    }
    g_off[i] = s[t] - v;
    if (t == 255) g_bsum[blockIdx.x] = s[t];
}

__global__ void k_scan2() {
    __shared__ int s[256];
    int t = threadIdx.x;
    int v = g_bsum[t];
    s[t] = v;
    __syncthreads();
    for (int off = 1; off < 256; off <<= 1) {
        int x = s[t];
        if (t >= off) x += s[t - off];
        __syncthreads();
        s[t] = x;
        __syncthreads();
    }
    g_bsum[t] = s[t] - v;   // exclusive
}

__global__ void k_scan3() {
    int i = blockIdx.x * 256 + threadIdx.x;
    int o = g_off[i] + g_bsum[blockIdx.x];
    g_off[i] = o;
    g_cursor[i] = o;
    g_offdeg[i] = (uint32_t)o | ((uint32_t)g_deg[i] << 21);
}

__global__ void k_fill(const int* __restrict__ esrc, const int* __restrict__ edst) {
    int e = blockIdx.x * 256 + threadIdx.x;
    if (e >= NEDGES) return;
    int s = esrc[e], d = edst[e];
    float nr = g_dinv[s] * g_dinv[d];
    int slot = atomicAdd(&g_cursor[d], 1);
    g_csre[slot] = make_float2(__int_as_float(s & (NPER - 1)), nr);
}

// ---------------- L2-gather aggregation (warp per node, R3-proven loop) ----------
// WRITE_C: also emit c[n] = sum of incoming norms (for conv2 global term).
template <bool WRITE_C>
__global__ __launch_bounds__(256) void k_agg64(const float* __restrict__ X,
                                               float* __restrict__ Y) {
    int node = blockIdx.x * 8 + (threadIdx.x >> 5);
    int lane = threadIdx.x & 31;
    const float2* xs = (const float2*)X;
    uint32_t od = g_offdeg[node];
    int off = od & 0x1FFFFF, deg = od >> 21;
    float dv = g_dinv[node];
    float sl = dv * dv;
    float2 xv = xs[node * 32 + lane];
    float2 acc = {sl * xv.x, sl * xv.y};
    float csum = sl;
    const int gbase = (node & ~(NPER - 1)) * 32;   // graph base in float2 units
    const float2* ep = &g_csre[off];
    #pragma unroll 2
    for (int j = 0; j < deg; j++) {
        float2 e = ep[j];                          // uniform LDG.64 (broadcast)
        int s = __float_as_int(e.x);
        float2 v = xs[gbase + s * 32 + lane];
        acc.x += e.y * v.x;
        acc.y += e.y * v.y;
        if (WRITE_C) csum += e.y;
    }
    ((float2*)Y)[node * 32 + lane] = acc;
    if (WRITE_C && lane == 0) g_c[node] = csum;
}

__global__ __launch_bounds__(256) void k_agg128(const float* __restrict__ X,
                                                float* __restrict__ Y) {
    int node = blockIdx.x * 8 + (threadIdx.x >> 5);
    int lane = threadIdx.x & 31;
    const float4* xs = (const float4*)X;
    uint32_t od = g_offdeg[node];
    int off = od & 0x1FFFFF, deg = od >> 21;
    float dv = g_dinv[node];
    float sl = dv * dv;
    float4 xv = xs[node * 32 + lane];
    float4 acc = {sl * xv.x, sl * xv.y, sl * xv.z, sl * xv.w};
    const int gbase = (node & ~(NPER - 1)) * 32;   // graph base in float4 units
    const float2* ep = &g_csre[off];
    #pragma unroll 2
    for (int j = 0; j < deg; j++) {
        float2 e = ep[j];                          // uniform LDG.64 (broadcast)
        int s = __float_as_int(e.x);
        float4 v = xs[gbase + s * 32 + lane];
        acc.x += e.y * v.x; acc.y += e.y * v.y;
        acc.z += e.y * v.z; acc.w += e.y * v.w;
    }
    ((float4*)Y)[node * 32 + lane] = acc;
}

// ---------------- 3xTF32 mma.sync GEMM: Y[128 rows/blk, 128] ----------------
template <int K, bool RELU, bool GLOB>
__global__ __launch_bounds__(256) void k_mgemm(
    const float* __restrict__ A, const float* __restrict__ W,
    const float* __restrict__ bias, float* __restrict__ Y) {
    extern __shared__ float sm[];
    const int PA = K + 4;
    float* sA = sm;                 // 128 * PA
    float* sB = sm + 128 * PA;      // K * 136
    const int tid = threadIdx.x;
    const int rbase = blockIdx.x * 128;

    for (int i = tid; i < 128 * (K / 4); i += 256) {
        int row = i / (K / 4), c = i % (K / 4);
        float4 v = *(const float4*)&A[(size_t)(rbase + row) * K + c * 4];
        *(float4*)&sA[row * PA + c * 4] = v;
    }
    for (int i = tid; i < K * 32; i += 256) {
        int row = i / 32, c = i % 32;
        *(float4*)&sB[row * 136 + c * 4] = *(const float4*)&W[row * 128 + c * 4];
    }
    __syncthreads();

    const int lane = tid & 31, wid = tid >> 5;
    const int gp = lane >> 2, tg = lane & 3;
    const int m0 = (wid & 3) * 32, n0 = (wid >> 2) * 64;

    float4 acc[2][8];
    #pragma unroll
    for (int mf = 0; mf < 2; mf++)
        #pragma unroll
        for (int f = 0; f < 8; f++) acc[mf][f] = make_float4(0.f, 0.f, 0.f, 0.f);

    for (int ks = 0; ks < K / 8; ks++) {
        const int kc = ks * 8;
        uint32_t ah[2][4], al[2][4];
        #pragma unroll
        for (int mf = 0; mf < 2; mf++) {
            int r0 = m0 + mf * 16 + gp;
            float x0 = sA[r0 * PA + kc + tg];
            float x1 = sA[(r0 + 8) * PA + kc + tg];
            float x2 = sA[r0 * PA + kc + tg + 4];
            float x3 = sA[(r0 + 8) * PA + kc + tg + 4];
            split_tf32(x0, ah[mf][0], al[mf][0]);
            split_tf32(x1, ah[mf][1], al[mf][1]);
            split_tf32(x2, ah[mf][2], al[mf][2]);
            split_tf32(x3, ah[mf][3], al[mf][3]);
        }
        #pragma unroll
        for (int f = 0; f < 8; f++) {
            int n = n0 + f * 8 + gp;
            float y0 = sB[(kc + tg) * 136 + n];
            float y1 = sB[(kc + tg + 4) * 136 + n];
            uint32_t bh[2], bl[2];
            split_tf32(y0, bh[0], bl[0]);
            split_tf32(y1, bh[1], bl[1]);
            #pragma unroll
            for (int mf = 0; mf < 2; mf++) {
                mma_tf32(acc[mf][f], ah[mf], bh);
                mma_tf32(acc[mf][f], ah[mf], bl);
                mma_tf32(acc[mf][f], al[mf], bh);
            }
        }
    }

    const float* gw = GLOB ? &g_gW[(rbase >> 10) * HID] : nullptr;
    #pragma unroll
    for (int mf = 0; mf < 2; mf++) {
        int r0 = rbase + m0 + mf * 16 + gp;
        int r1 = r0 + 8;
        float cc0 = GLOB ? g_c[r0] : 0.f;
        float cc1 = GLOB ? g_c[r1] : 0.f;
        #pragma unroll
        for (int f = 0; f < 8; f++) {
            int c = n0 + f * 8 + 2 * tg;
            float2 bv = *(const float2*)&bias[c];
            float4 a = acc[mf][f];
            float2 o0 = {a.x + bv.x, a.y + bv.y};
            float2 o1 = {a.z + bv.x, a.w + bv.y};
            if (GLOB) {
                float2 gv = *(const float2*)&gw[c];
                o0.x += cc0 * gv.x; o0.y += cc0 * gv.y;
                o1.x += cc1 * gv.x; o1.y += cc1 * gv.y;
            }
            if (RELU) {
                o0.x = fmaxf(o0.x, 0.f); o0.y = fmaxf(o0.y, 0.f);
                o1.x = fmaxf(o1.x, 0.f); o1.y = fmaxf(o1.y, 0.f);
            }
            *(float2*)&Y[(size_t)r0 * 128 + c] = o0;
            *(float2*)&Y[(size_t)r1 * 128 + c] = o1;
        }
    }
}

// ---------------- max pool (two stage) + global path matmuls ----------------
__global__ void k_maxpool1(const float* __restrict__ H) {
    int g = blockIdx.x >> 3, s = blockIdx.x & 7, f = threadIdx.x;
    const float* p = H + ((size_t)g * NPER + s * 128) * HID + f;
    float m = -CUDART_INF_F;
    for (int i = 0; i < 128; i++) m = fmaxf(m, p[(size_t)i * HID]);
    g_mpp[(g * 8 + s) * HID + f] = m;
}

__global__ void k_maxpool2() {
    int g = blockIdx.x, f = threadIdx.x;
    float m = -CUDART_INF_F;
    #pragma unroll
    for (int s = 0; s < 8; s++) m = fmaxf(m, g_mpp[(g * 8 + s) * HID + f]);
    g_mp[g * HID + f] = m;
}

__global__ void k_globs(const float* __restrict__ Wf, const float* __restrict__ bf,
                        const float* __restrict__ W2) {
    __shared__ float s1[HID];
    __shared__ float s2[HID];
    int g = blockIdx.x, t = threadIdx.x;
    s1[t] = g_mp[g * HID + t];
    __syncthreads();
    float acc = bf[t];
    for (int k = 0; k < HID; k++) acc += s1[k] * Wf[k * HID + t];
    s2[t] = acc;
    __syncthreads();
    float a2 = 0.f;
    for (int k = 0; k < HID; k++) a2 += s2[k] * W2[(HID + k) * HID + t];
    g_gW[g * HID + t] = a2;
}

// ---------------- final projection ----------------
__global__ void k_z(const float* __restrict__ H, const float* __restrict__ W3) {
    int node = blockIdx.x * 8 + (threadIdx.x >> 5);
    int lane = threadIdx.x & 31;
    float4 h = ((const float4*)H)[node * 32 + lane];
    float4 w = ((const float4*)W3)[lane];
    float d = h.x * w.x + h.y * w.y + h.z * w.z + h.w * w.w;
    #pragma unroll
    for (int o = 16; o; o >>= 1) d += __shfl_xor_sync(0xffffffffu, d, o);
    if (lane == 0) g_z[node] = d;
}

// ---------------- fused logit + per-graph top-K mask ----------------
__global__ __launch_bounds__(256) void k_logitk(const float* __restrict__ b3,
                                                float* __restrict__ out) {
    __shared__ float sz[NPER];
    __shared__ float slog[NPER];
    __shared__ float v[NPER];
    __shared__ float wmax[8];
    __shared__ float sth;
    __shared__ int sidx;
    const int g = blockIdx.x, t = threadIdx.x;
    const int lane = t & 31, warp = t >> 5;
    const float bb = b3[0];

    for (int i = t; i < NPER; i += 256) sz[i] = g_z[g * NPER + i];
    __syncthreads();

    for (int ln = warp; ln < NPER; ln += 8) {
        uint32_t od = g_offdeg[g * NPER + ln];
        int off = od & 0x1FFFFF, deg = od >> 21;
        float part = 0.f;
        for (int j = lane; j < deg; j += 32) {
            float2 e = g_csre[off + j];
            part += e.y * sz[__float_as_int(e.x)];
        }
        #pragma unroll
        for (int o = 16; o; o >>= 1) part += __shfl_xor_sync(0xffffffffu, part, o);
        if (lane == 0) {
            float dv = g_dinv[g * NPER + ln];
            float lv = part + dv * dv * sz[ln] + bb;
            slog[ln] = lv;
            v[ln] = lv;
        }
    }
    __syncthreads();

    for (int it = 0; it < TOPK; it++) {
        float m = -CUDART_INF_F;
        for (int i = t; i < NPER; i += 256) m = fmaxf(m, v[i]);
        #pragma unroll
        for (int o = 16; o; o >>= 1) m = fmaxf(m, __shfl_xor_sync(0xffffffffu, m, o));
        if (lane == 0) wmax[warp] = m;
        __syncthreads();
        if (t == 0) {
            float mm = wmax[0];
            #pragma unroll
            for (int w = 1; w < 8; w++) mm = fmaxf(mm, wmax[w]);
            sth = mm;
            sidx = 0x7fffffff;
        }
        __syncthreads();
        float mm = sth;
        for (int i = t; i < NPER; i += 256)
            if (v[i] == mm) atomicMin(&sidx, i);
        __syncthreads();
        if (t == 0) v[sidx] = -CUDART_INF_F;
        __syncthreads();
    }
    float th = sth;
    for (int i = t; i < NPER; i += 256)
        out[g * NPER + i] = (slog[i] >= th) ? 1.0f : 0.0f;
}

// ---------------- host launcher ----------------
extern "C" void kernel_launch(void* const* d_in, const int* in_sizes, int n_in,
                              void* d_out, int out_size) {
    const float* x    = (const float*)d_in[0];
    const int*   esrc = (const int*)d_in[1];
    const int*   edst = (const int*)d_in[2];
    const float* W0 = (const float*)d_in[4];
    const float* b0 = (const float*)d_in[5];
    const float* W1 = (const float*)d_in[6];
    const float* b1 = (const float*)d_in[7];
    const float* Wf = (const float*)d_in[8];
    const float* bf = (const float*)d_in[9];
    const float* W2 = (const float*)d_in[10];
    const float* b2 = (const float*)d_in[11];
    const float* W3 = (const float*)d_in[12];
    const float* b3 = (const float*)d_in[13];
    float* out = (float*)d_out;

    float *T0, *T1, *T2;
    int* degp;
    cudaGetSymbolAddress((void**)&T0, g_T0);
    cudaGetSymbolAddress((void**)&T1, g_T1);
    cudaGetSymbolAddress((void**)&T2, g_T2);
    cudaGetSymbolAddress((void**)&degp, g_deg);

    const int SM64  = (128 * 68 + 64 * 136) * 4;     // 69632
    const int SM128 = (128 * 132 + 128 * 136) * 4;   // 137216
    cudaFuncSetAttribute(k_mgemm<64, true, false>,  cudaFuncAttributeMaxDynamicSharedMemorySize, SM64);
    cudaFuncSetAttribute(k_mgemm<128, true, false>, cudaFuncAttributeMaxDynamicSharedMemorySize, SM128);
    cudaFuncSetAttribute(k_mgemm<128, true, true>,  cudaFuncAttributeMaxDynamicSharedMemorySize, SM128);

    // --- CSR + norms ---
    cudaMemsetAsync(degp, 0, NNODES * sizeof(int));
    k_hist<<<NEDGES / 256, 256>>>(edst);
    k_scan1<<<256, 256>>>();
    k_scan2<<<1, 256>>>();
    k_scan3<<<256, 256>>>();
    k_fill<<<NEDGES / 256, 256>>>(esrc, edst);

    // --- conv0: h0 = relu(agg(x) @ W0 + b0) (+ c vector) ---
    k_agg64<true><<<NNODES / 8, 256>>>(x, T2);
    k_mgemm<64, true, false><<<NNODES / 128, 256, SM64>>>(T2, W0, b0, T0);

    // --- global path ---
    k_maxpool1<<<NGRAPH * 8, HID>>>(T0);
    k_maxpool2<<<NGRAPH, HID>>>();
    k_globs<<<NGRAPH, HID>>>(Wf, bf, W2);

    // --- conv1 (applied twice with same weights) ---
    k_agg128<<<NNODES / 8, 256>>>(T0, T1);
    k_mgemm<128, true, false><<<NNODES / 128, 256, SM128>>>(T1, W1, b1, T2);
    k_agg128<<<NNODES / 8, 256>>>(T2, T1);
    k_mgemm<128, true, false><<<NNODES / 128, 256, SM128>>>(T1, W1, b1, T0);

    // --- conv2 on concat: relu(agg(h) @ W2_top + c_n * gW + b2) ---
    k_agg128<<<NNODES / 8, 256>>>(T0, T1);
    k_mgemm<128, true, true><<<NNODES / 128, 256, SM128>>>(T1, W2, b2, T2);

    // --- conv3 (out=1): z = h @ W3, then fused logit + top-10 mask ---
    k_z<<<NNODES / 8, 256>>>(T2, W3);
    k_logitk<<<NGRAPH, 256>>>(b3, out);
}

// round 7
// speedup vs baseline: 2.1093x; 1.3353x over previous
#include <cuda_runtime.h>
#include <math_constants.h>
#include <cstdint>

#define NNODES 65536
#define NEDGES 1048576
#define NGRAPH 64
#define NPER   1024
#define FEAT   64
#define HID    128
#define TOPK   10

// ---------------- device scratch (no allocations allowed) ----------------
__device__ int   g_deg[NNODES];
__device__ float g_dinv[NNODES];
__device__ int   g_off[NNODES];
__device__ int   g_cursor[NNODES];
__device__ int   g_bsum[256];
__device__ int   g_csrsrc[NEDGES];
__device__ float g_csrnrm[NEDGES];
__device__ float g_c[NNODES];
__device__ float g_T0[NNODES * HID];
__device__ float g_T1[NNODES * HID];
__device__ float g_mpp[NGRAPH * 8 * HID];
__device__ float g_gW[NGRAPH * HID];
__device__ float g_z[NNODES];
__device__ float g_logit[NNODES];

// ---------------- tf32 helpers ----------------
__device__ __forceinline__ void split_tf32(float a, uint32_t& hi, uint32_t& lo) {
    asm("cvt.rna.tf32.f32 %0, %1;" : "=r"(hi) : "f"(a));
    float r = a - __uint_as_float(hi);
    asm("cvt.rna.tf32.f32 %0, %1;" : "=r"(lo) : "f"(r));
}

__device__ __forceinline__ void mma_tf32(float4& d, const uint32_t a[4], const uint32_t b[2]) {
    asm volatile(
        "mma.sync.aligned.m16n8k8.row.col.f32.tf32.tf32.f32 "
        "{%0,%1,%2,%3}, {%4,%5,%6,%7}, {%8,%9}, {%0,%1,%2,%3};"
        : "+f"(d.x), "+f"(d.y), "+f"(d.z), "+f"(d.w)
        : "r"(a[0]), "r"(a[1]), "r"(a[2]), "r"(a[3]), "r"(b[0]), "r"(b[1]));
}

// ---------------- CSR construction ----------------
__global__ void k_hist(const int* __restrict__ edst) {
    int e = blockIdx.x * 256 + threadIdx.x;
    if (e < NEDGES) atomicAdd(&g_deg[edst[e]], 1);
}

__global__ void k_scan1() {
    __shared__ int s[256];
    int t = threadIdx.x;
    int i = blockIdx.x * 256 + t;
    int v = g_deg[i];
    g_dinv[i] = rsqrtf((float)(v + 1));
    s[t] = v;
    __syncthreads();
    for (int off = 1; off < 256; off <<= 1) {
        int x = s[t];
        if (t >= off) x += s[t - off];
        __syncthreads();
        s[t] = x;
        __syncthreads();
    }
    g_off[i] = s[t] - v;
    if (t == 255) g_bsum[blockIdx.x] = s[t];
}

__global__ void k_scan2() {
    __shared__ int s[256];
    int t = threadIdx.x;
    int v = g_bsum[t];
    s[t] = v;
    __syncthreads();
    for (int off = 1; off < 256; off <<= 1) {
        int x = s[t];
        if (t >= off) x += s[t - off];
        __syncthreads();
        s[t] = x;
        __syncthreads();
    }
    g_bsum[t] = s[t] - v;   // exclusive
}

__global__ void k_scan3() {
    int i = blockIdx.x * 256 + threadIdx.x;
    int o = g_off[i] + g_bsum[blockIdx.x];
    g_off[i] = o;
    g_cursor[i] = o;
}

__global__ void k_fill(const int* __restrict__ esrc, const int* __restrict__ edst) {
    int e = blockIdx.x * 256 + threadIdx.x;
    if (e >= NEDGES) return;
    int s = esrc[e], d = edst[e];
    float nr = g_dinv[s] * g_dinv[d];
    int slot = atomicAdd(&g_cursor[d], 1);
    g_csrsrc[slot] = s;
    g_csrnrm[slot] = nr;
}

// ---------------- sparse aggregations (warp per node, R3-proven loops) ----------
// WRITE_C: also emit c[n] = sum of incoming norms (replaces k_cvec).
template <bool WRITE_C>
__global__ __launch_bounds__(256) void k_agg64(const float* __restrict__ X,
                                               float* __restrict__ Y) {
    int node = blockIdx.x * 8 + (threadIdx.x >> 5);
    int lane = threadIdx.x & 31;
    const float2* xs = (const float2*)X;
    float dv = g_dinv[node];
    float2 xv = xs[node * 32 + lane];
    float2 acc;
    acc.x = dv * dv * xv.x;
    acc.y = dv * dv * xv.y;
    float csum = dv * dv;
    int jb = g_off[node], je = jb + g_deg[node];
    #pragma unroll 2
    for (int j = jb; j < je; j++) {
        int s = g_csrsrc[j];
        float nr = g_csrnrm[j];
        float2 v = xs[s * 32 + lane];
        acc.x += nr * v.x;
        acc.y += nr * v.y;
        if (WRITE_C) csum += nr;
    }
    ((float2*)Y)[node * 32 + lane] = acc;
    if (WRITE_C && lane == 0) g_c[node] = csum;
}

__global__ __launch_bounds__(256) void k_agg128(const float* __restrict__ X,
                                                float* __restrict__ Y) {
    int node = blockIdx.x * 8 + (threadIdx.x >> 5);
    int lane = threadIdx.x & 31;
    const float4* xs = (const float4*)X;
    float dv = g_dinv[node];
    float4 xv = xs[node * 32 + lane];
    float4 acc;
    float sl = dv * dv;
    acc.x = sl * xv.x; acc.y = sl * xv.y; acc.z = sl * xv.z; acc.w = sl * xv.w;
    int jb = g_off[node], je = jb + g_deg[node];
    #pragma unroll 2
    for (int j = jb; j < je; j++) {
        int s = g_csrsrc[j];
        float nr = g_csrnrm[j];
        float4 v = xs[s * 32 + lane];
        acc.x += nr * v.x; acc.y += nr * v.y; acc.z += nr * v.z; acc.w += nr * v.w;
    }
    ((float4*)Y)[node * 32 + lane] = acc;
}

// ---------------- 3xTF32 mma.sync GEMM: per-block 128 rows x 128 cols --------------
// MAXP: fold maxpool stage-1 into epilogue (block = one graph slice of 128 rows).
// ZOUT: skip Y store; instead compute z[row] = h_row . W3 (deterministic smem reduce).
template <int K, bool RELU, bool GLOB, bool MAXP, bool ZOUT>
__global__ __launch_bounds__(256) void k_mgemm(
    const float* __restrict__ A, const float* __restrict__ W,
    const float* __restrict__ bias, float* __restrict__ Y,
    const float* __restrict__ W3) {
    extern __shared__ float sm[];
    __shared__ int   smax[128];
    __shared__ float szp[128][8];
    const int PA = K + 4;
    float* sA = sm;                 // 128 * PA
    float* sB = sm + 128 * PA;      // K * 136
    const int tid = threadIdx.x;
    const int rbase = blockIdx.x * 128;

    if (MAXP && tid < 128) smax[tid] = 0;

    for (int i = tid; i < 128 * (K / 4); i += 256) {
        int row = i / (K / 4), c = i % (K / 4);
        float4 v = *(const float4*)&A[(size_t)(rbase + row) * K + c * 4];
        *(float4*)&sA[row * PA + c * 4] = v;
    }
    for (int i = tid; i < K * 32; i += 256) {
        int row = i / 32, c = i % 32;
        *(float4*)&sB[row * 136 + c * 4] = *(const float4*)&W[row * 128 + c * 4];
    }
    __syncthreads();

    const int lane = tid & 31, wid = tid >> 5;
    const int gp = lane >> 2, tg = lane & 3;
    const int m0 = (wid & 3) * 32, n0 = (wid >> 2) * 64;

    float4 acc[2][8];
    #pragma unroll
    for (int mf = 0; mf < 2; mf++)
        #pragma unroll
        for (int f = 0; f < 8; f++) acc[mf][f] = make_float4(0.f, 0.f, 0.f, 0.f);

    for (int ks = 0; ks < K / 8; ks++) {
        const int kc = ks * 8;
        uint32_t ah[2][4], al[2][4];
        #pragma unroll
        for (int mf = 0; mf < 2; mf++) {
            int r0 = m0 + mf * 16 + gp;
            float x0 = sA[r0 * PA + kc + tg];
            float x1 = sA[(r0 + 8) * PA + kc + tg];
            float x2 = sA[r0 * PA + kc + tg + 4];
            float x3 = sA[(r0 + 8) * PA + kc + tg + 4];
            split_tf32(x0, ah[mf][0], al[mf][0]);
            split_tf32(x1, ah[mf][1], al[mf][1]);
            split_tf32(x2, ah[mf][2], al[mf][2]);
            split_tf32(x3, ah[mf][3], al[mf][3]);
        }
        #pragma unroll
        for (int f = 0; f < 8; f++) {
            int n = n0 + f * 8 + gp;
            float y0 = sB[(kc + tg) * 136 + n];
            float y1 = sB[(kc + tg + 4) * 136 + n];
            uint32_t bh[2], bl[2];
            split_tf32(y0, bh[0], bl[0]);
            split_tf32(y1, bh[1], bl[1]);
            #pragma unroll
            for (int mf = 0; mf < 2; mf++) {
                mma_tf32(acc[mf][f], ah[mf], bh);
                mma_tf32(acc[mf][f], ah[mf], bl);
                mma_tf32(acc[mf][f], al[mf], bh);
            }
        }
    }

    float colmax[8][2];
    if (MAXP) {
        #pragma unroll
        for (int f = 0; f < 8; f++) { colmax[f][0] = 0.f; colmax[f][1] = 0.f; }
    }
    float zp[2][2] = {{0.f, 0.f}, {0.f, 0.f}};

    const float* gw = GLOB ? &g_gW[(rbase >> 10) * HID] : nullptr;
    #pragma unroll
    for (int mf = 0; mf < 2; mf++) {
        int r0 = rbase + m0 + mf * 16 + gp;
        int r1 = r0 + 8;
        float cc0 = GLOB ? g_c[r0] : 0.f;
        float cc1 = GLOB ? g_c[r1] : 0.f;
        #pragma unroll
        for (int f = 0; f < 8; f++) {
            int c = n0 + f * 8 + 2 * tg;
            float2 bv = *(const float2*)&bias[c];
            float4 a = acc[mf][f];
            float2 o0 = {a.x + bv.x, a.y + bv.y};
            float2 o1 = {a.z + bv.x, a.w + bv.y};
            if (GLOB) {
                float2 gv = *(const float2*)&gw[c];
                o0.x += cc0 * gv.x; o0.y += cc0 * gv.y;
                o1.x += cc1 * gv.x; o1.y += cc1 * gv.y;
            }
            if (RELU) {
                o0.x = fmaxf(o0.x, 0.f); o0.y = fmaxf(o0.y, 0.f);
                o1.x = fmaxf(o1.x, 0.f); o1.y = fmaxf(o1.y, 0.f);
            }
            if (!ZOUT) {
                *(float2*)&Y[(size_t)r0 * 128 + c] = o0;
                *(float2*)&Y[(size_t)r1 * 128 + c] = o1;
            }
            if (MAXP) {
                colmax[f][0] = fmaxf(colmax[f][0], fmaxf(o0.x, o1.x));
                colmax[f][1] = fmaxf(colmax[f][1], fmaxf(o0.y, o1.y));
            }
            if (ZOUT) {
                float w3a = W3[c], w3b = W3[c + 1];
                zp[mf][0] += o0.x * w3a + o0.y * w3b;
                zp[mf][1] += o1.x * w3a + o1.y * w3b;
            }
        }
    }

    if (MAXP) {
        #pragma unroll
        for (int f = 0; f < 8; f++) {
            int c = n0 + f * 8 + 2 * tg;
            atomicMax(&smax[c],     __float_as_int(colmax[f][0]));
            atomicMax(&smax[c + 1], __float_as_int(colmax[f][1]));
        }
        __syncthreads();
        if (tid < 128) g_mpp[(size_t)blockIdx.x * HID + tid] = __int_as_float(smax[tid]);
    }

    if (ZOUT) {
        int slot = ((wid >> 2) << 2) | tg;
        #pragma unroll
        for (int mf = 0; mf < 2; mf++) {
            szp[m0 + mf * 16 + gp][slot]     = zp[mf][0];
            szp[m0 + mf * 16 + gp + 8][slot] = zp[mf][1];
        }
        __syncthreads();
        if (tid < 128) {
            float z = 0.f;
            #pragma unroll
            for (int k = 0; k < 8; k++) z += szp[tid][k];
            g_z[rbase + tid] = z;
        }
    }
}

// ---------------- fused maxpool stage-2 + global path matmuls ----------------
__global__ void k_globs2(const float* __restrict__ Wf, const float* __restrict__ bf,
                         const float* __restrict__ W2) {
    __shared__ float s1[HID];
    __shared__ float s2[HID];
    int g = blockIdx.x, t = threadIdx.x;
    float m = -CUDART_INF_F;
    #pragma unroll
    for (int s = 0; s < 8; s++) m = fmaxf(m, g_mpp[(g * 8 + s) * HID + t]);
    s1[t] = m;
    __syncthreads();
    float acc = bf[t];
    for (int k = 0; k < HID; k++) acc += s1[k] * Wf[k * HID + t];
    s2[t] = acc;
    __syncthreads();
    float a2 = 0.f;
    for (int k = 0; k < HID; k++) a2 += s2[k] * W2[(HID + k) * HID + t];
    g_gW[g * HID + t] = a2;
}

// ---------------- logit aggregation (R3-proven) ----------------
__global__ void k_logit(const float* __restrict__ b3) {
    int node = blockIdx.x * 8 + (threadIdx.x >> 5);
    int lane = threadIdx.x & 31;
    int jb = g_off[node], je = jb + g_deg[node];
    float part = 0.f;
    for (int j = jb + lane; j < je; j += 32)
        part += g_csrnrm[j] * g_z[g_csrsrc[j]];
    #pragma unroll
    for (int o = 16; o; o >>= 1) part += __shfl_xor_sync(0xffffffffu, part, o);
    if (lane == 0) {
        float dv = g_dinv[node];
        g_logit[node] = part + dv * dv * g_z[node] + b3[0];
    }
}

// ---------------- per-graph top-K threshold + mask (R3-proven) ----------------
__global__ void k_topk(float* __restrict__ out) {
    __shared__ float v[NPER];
    __shared__ float wmax[8];
    __shared__ float sth;
    __shared__ int sidx;
    int g = blockIdx.x, t = threadIdx.x;
    int lane = t & 31, warp = t >> 5;
    for (int i = t; i < NPER; i += 256) v[i] = g_logit[g * NPER + i];
    __syncthreads();
    for (int it = 0; it < TOPK; it++) {
        float m = -CUDART_INF_F;
        for (int i = t; i < NPER; i += 256) m = fmaxf(m, v[i]);
        #pragma unroll
        for (int o = 16; o; o >>= 1) m = fmaxf(m, __shfl_xor_sync(0xffffffffu, m, o));
        if (lane == 0) wmax[warp] = m;
        __syncthreads();
        if (t == 0) {
            float mm = wmax[0];
            #pragma unroll
            for (int w = 1; w < 8; w++) mm = fmaxf(mm, wmax[w]);
            sth = mm;
            sidx = 0x7fffffff;
        }
        __syncthreads();
        float mm = sth;
        for (int i = t; i < NPER; i += 256)
            if (v[i] == mm) atomicMin(&sidx, i);
        __syncthreads();
        if (t == 0) v[sidx] = -CUDART_INF_F;
        __syncthreads();
    }
    float th = sth;
    for (int i = t; i < NPER; i += 256)
        out[g * NPER + i] = (g_logit[g * NPER + i] >= th) ? 1.0f : 0.0f;
}

// ---------------- host launcher ----------------
extern "C" void kernel_launch(void* const* d_in, const int* in_sizes, int n_in,
                              void* d_out, int out_size) {
    const float* x    = (const float*)d_in[0];
    const int*   esrc = (const int*)d_in[1];
    const int*   edst = (const int*)d_in[2];
    const float* W0 = (const float*)d_in[4];
    const float* b0 = (const float*)d_in[5];
    const float* W1 = (const float*)d_in[6];
    const float* b1 = (const float*)d_in[7];
    const float* Wf = (const float*)d_in[8];
    const float* bf = (const float*)d_in[9];
    const float* W2 = (const float*)d_in[10];
    const float* b2 = (const float*)d_in[11];
    const float* W3 = (const float*)d_in[12];
    const float* b3 = (const float*)d_in[13];
    float* out = (float*)d_out;

    float *T0, *T1;
    int* degp;
    cudaGetSymbolAddress((void**)&T0, g_T0);
    cudaGetSymbolAddress((void**)&T1, g_T1);
    cudaGetSymbolAddress((void**)&degp, g_deg);

    const int SM64  = (128 * 68 + 64 * 136) * 4;     // 69632
    const int SM128 = (128 * 132 + 128 * 136) * 4;   // 137216
    cudaFuncSetAttribute(k_mgemm<64, true, false, true, false>,
                         cudaFuncAttributeMaxDynamicSharedMemorySize, SM64);
    cudaFuncSetAttribute(k_mgemm<128, true, false, false, false>,
                         cudaFuncAttributeMaxDynamicSharedMemorySize, SM128);
    cudaFuncSetAttribute(k_mgemm<128, true, true, false, true>,
                         cudaFuncAttributeMaxDynamicSharedMemorySize, SM128);

    // --- CSR + norms ---
    cudaMemsetAsync(degp, 0, NNODES * sizeof(int));
    k_hist<<<NEDGES / 256, 256>>>(edst);
    k_scan1<<<256, 256>>>();
    k_scan2<<<1, 256>>>();
    k_scan3<<<256, 256>>>();
    k_fill<<<NEDGES / 256, 256>>>(esrc, edst);

    // --- conv0: h0 = relu(agg(x) @ W0 + b0); epilogue emits maxpool partials ---
    k_agg64<true><<<NNODES / 8, 256>>>(x, T1);
    k_mgemm<64, true, false, true, false><<<NNODES / 128, 256, SM64>>>(T1, W0, b0, T0, nullptr);

    // --- global path: mp2 + (mp @ Wf + bf) @ W2_bottom ---
    k_globs2<<<NGRAPH, HID>>>(Wf, bf, W2);

    // --- conv1 (applied twice with same weights) ---
    k_agg128<<<NNODES / 8, 256>>>(T0, T1);
    k_mgemm<128, true, false, false, false><<<NNODES / 128, 256, SM128>>>(T1, W1, b1, T0, nullptr);
    k_agg128<<<NNODES / 8, 256>>>(T0, T1);
    k_mgemm<128, true, false, false, false><<<NNODES / 128, 256, SM128>>>(T1, W1, b1, T0, nullptr);

    // --- conv2 + conv3 projection fused: epilogue computes z = h . W3, no h store ---
    k_agg128<<<NNODES / 8, 256>>>(T0, T1);
    k_mgemm<128, true, true, false, true><<<NNODES / 128, 256, SM128>>>(T1, W2, b2, nullptr, W3);

    // --- logit = agg(z) + b3, then per-graph top-10 mask ---
    k_logit<<<NNODES / 8, 256>>>(b3);
    k_topk<<<NGRAPH, 256>>>(out);
}

// round 8
// speedup vs baseline: 2.1155x; 1.0029x over previous
#include <cuda_runtime.h>
#include <math_constants.h>
#include <cstdint>

#define NNODES 65536
#define NEDGES 1048576
#define NGRAPH 64
#define NPER   1024
#define FEAT   64
#define HID    128
#define TOPK   10

// ---------------- device scratch (no allocations allowed) ----------------
__device__ int   g_deg[NNODES];
__device__ float g_dinv[NNODES];
__device__ int   g_off[NNODES];
__device__ int   g_cursor[NNODES];
__device__ int   g_bsum[256];
__device__ int   g_csrsrc[NEDGES];
__device__ float g_csrnrm[NEDGES];
__device__ float g_c[NNODES];
__device__ float g_T0[NNODES * HID];
__device__ float g_T1[NNODES * HID];
__device__ float g_mpp[NGRAPH * 8 * HID];
__device__ float g_gW[NGRAPH * HID];
__device__ float g_z[NNODES];
__device__ float g_logit[NNODES];

// ---------------- tf32 helpers ----------------
__device__ __forceinline__ void split_tf32(float a, uint32_t& hi, uint32_t& lo) {
    asm("cvt.rna.tf32.f32 %0, %1;" : "=r"(hi) : "f"(a));
    float r = a - __uint_as_float(hi);
    asm("cvt.rna.tf32.f32 %0, %1;" : "=r"(lo) : "f"(r));
}

__device__ __forceinline__ void mma_tf32(float4& d, const uint32_t a[4], const uint32_t b[2]) {
    asm volatile(
        "mma.sync.aligned.m16n8k8.row.col.f32.tf32.tf32.f32 "
        "{%0,%1,%2,%3}, {%4,%5,%6,%7}, {%8,%9}, {%0,%1,%2,%3};"
        : "+f"(d.x), "+f"(d.y), "+f"(d.z), "+f"(d.w)
        : "r"(a[0]), "r"(a[1]), "r"(a[2]), "r"(a[3]), "r"(b[0]), "r"(b[1]));
}

// ---------------- CSR construction ----------------
__global__ void k_hist(const int* __restrict__ edst) {
    int e = blockIdx.x * 256 + threadIdx.x;
    if (e < NEDGES) atomicAdd(&g_deg[edst[e]], 1);
}

__global__ void k_scan1() {
    __shared__ int s[256];
    int t = threadIdx.x;
    int i = blockIdx.x * 256 + t;
    int v = g_deg[i];
    g_dinv[i] = rsqrtf((float)(v + 1));
    s[t] = v;
    __syncthreads();
    for (int off = 1; off < 256; off <<= 1) {
        int x = s[t];
        if (t >= off) x += s[t - off];
        __syncthreads();
        s[t] = x;
        __syncthreads();
    }
    g_off[i] = s[t] - v;
    if (t == 255) g_bsum[blockIdx.x] = s[t];
}

__global__ void k_scan2() {
    __shared__ int s[256];
    int t = threadIdx.x;
    int v = g_bsum[t];
    s[t] = v;
    __syncthreads();
    for (int off = 1; off < 256; off <<= 1) {
        int x = s[t];
        if (t >= off) x += s[t - off];
        __syncthreads();
        s[t] = x;
        __syncthreads();
    }
    g_bsum[t] = s[t] - v;   // exclusive
}

__global__ void k_scan3() {
    int i = blockIdx.x * 256 + threadIdx.x;
    int o = g_off[i] + g_bsum[blockIdx.x];
    g_off[i] = o;
    g_cursor[i] = o;
}

__global__ void k_fill(const int* __restrict__ esrc, const int* __restrict__ edst) {
    int e = blockIdx.x * 256 + threadIdx.x;
    if (e >= NEDGES) return;
    int s = esrc[e], d = edst[e];
    float nr = g_dinv[s] * g_dinv[d];
    int slot = atomicAdd(&g_cursor[d], 1);
    g_csrsrc[slot] = s;
    g_csrnrm[slot] = nr;
}

// ---------------- sparse aggregations (warp per node, R3-proven loops) ----------
// WRITE_C: also emit c[n] = sum of incoming norms (replaces k_cvec).
template <bool WRITE_C>
__global__ __launch_bounds__(256) void k_agg64(const float* __restrict__ X,
                                               float* __restrict__ Y) {
    int node = blockIdx.x * 8 + (threadIdx.x >> 5);
    int lane = threadIdx.x & 31;
    const float2* xs = (const float2*)X;
    float dv = g_dinv[node];
    float2 xv = xs[node * 32 + lane];
    float2 acc;
    acc.x = dv * dv * xv.x;
    acc.y = dv * dv * xv.y;
    float csum = dv * dv;
    int jb = g_off[node], je = jb + g_deg[node];
    #pragma unroll 2
    for (int j = jb; j < je; j++) {
        int s = g_csrsrc[j];
        float nr = g_csrnrm[j];
        float2 v = xs[s * 32 + lane];
        acc.x += nr * v.x;
        acc.y += nr * v.y;
        if (WRITE_C) csum += nr;
    }
    ((float2*)Y)[node * 32 + lane] = acc;
    if (WRITE_C && lane == 0) g_c[node] = csum;
}

__global__ __launch_bounds__(256) void k_agg128(const float* __restrict__ X,
                                                float* __restrict__ Y) {
    int node = blockIdx.x * 8 + (threadIdx.x >> 5);
    int lane = threadIdx.x & 31;
    const float4* xs = (const float4*)X;
    float dv = g_dinv[node];
    float4 xv = xs[node * 32 + lane];
    float4 acc;
    float sl = dv * dv;
    acc.x = sl * xv.x; acc.y = sl * xv.y; acc.z = sl * xv.z; acc.w = sl * xv.w;
    int jb = g_off[node], je = jb + g_deg[node];
    #pragma unroll 2
    for (int j = jb; j < je; j++) {
        int s = g_csrsrc[j];
        float nr = g_csrnrm[j];
        float4 v = xs[s * 32 + lane];
        acc.x += nr * v.x; acc.y += nr * v.y; acc.z += nr * v.z; acc.w += nr * v.w;
    }
    ((float4*)Y)[node * 32 + lane] = acc;
}

// ---------------- 3xTF32 mma.sync GEMM: per-block 128 rows x 128 cols --------------
// MAXP: fold maxpool stage-1 into epilogue (block = one graph slice of 128 rows).
// ZOUT: skip Y store; instead compute z[row] = h_row . W3 (deterministic smem reduce).
template <int K, bool RELU, bool GLOB, bool MAXP, bool ZOUT>
__global__ __launch_bounds__(256) void k_mgemm(
    const float* __restrict__ A, const float* __restrict__ W,
    const float* __restrict__ bias, float* __restrict__ Y,
    const float* __restrict__ W3) {
    extern __shared__ float sm[];
    __shared__ int   smax[128];
    __shared__ float szp[128][8];
    const int PA = K + 4;
    float* sA = sm;                 // 128 * PA
    float* sB = sm + 128 * PA;      // K * 136
    const int tid = threadIdx.x;
    const int rbase = blockIdx.x * 128;

    if (MAXP && tid < 128) smax[tid] = 0;

    for (int i = tid; i < 128 * (K / 4); i += 256) {
        int row = i / (K / 4), c = i % (K / 4);
        float4 v = *(const float4*)&A[(size_t)(rbase + row) * K + c * 4];
        *(float4*)&sA[row * PA + c * 4] = v;
    }
    for (int i = tid; i < K * 32; i += 256) {
        int row = i / 32, c = i % 32;
        *(float4*)&sB[row * 136 + c * 4] = *(const float4*)&W[row * 128 + c * 4];
    }
    __syncthreads();

    const int lane = tid & 31, wid = tid >> 5;
    const int gp = lane >> 2, tg = lane & 3;
    const int m0 = (wid & 3) * 32, n0 = (wid >> 2) * 64;

    float4 acc[2][8];
    #pragma unroll
    for (int mf = 0; mf < 2; mf++)
        #pragma unroll
        for (int f = 0; f < 8; f++) acc[mf][f] = make_float4(0.f, 0.f, 0.f, 0.f);

    for (int ks = 0; ks < K / 8; ks++) {
        const int kc = ks * 8;
        uint32_t ah[2][4], al[2][4];
        #pragma unroll
        for (int mf = 0; mf < 2; mf++) {
            int r0 = m0 + mf * 16 + gp;
            float x0 = sA[r0 * PA + kc + tg];
            float x1 = sA[(r0 + 8) * PA + kc + tg];
            float x2 = sA[r0 * PA + kc + tg + 4];
            float x3 = sA[(r0 + 8) * PA + kc + tg + 4];
            split_tf32(x0, ah[mf][0], al[mf][0]);
            split_tf32(x1, ah[mf][1], al[mf][1]);
            split_tf32(x2, ah[mf][2], al[mf][2]);
            split_tf32(x3, ah[mf][3], al[mf][3]);
        }
        #pragma unroll
        for (int f = 0; f < 8; f++) {
            int n = n0 + f * 8 + gp;
            float y0 = sB[(kc + tg) * 136 + n];
            float y1 = sB[(kc + tg + 4) * 136 + n];
            uint32_t bh[2], bl[2];
            split_tf32(y0, bh[0], bl[0]);
            split_tf32(y1, bh[1], bl[1]);
            #pragma unroll
            for (int mf = 0; mf < 2; mf++) {
                mma_tf32(acc[mf][f], ah[mf], bh);
                mma_tf32(acc[mf][f], ah[mf], bl);
                mma_tf32(acc[mf][f], al[mf], bh);
            }
        }
    }

    float colmax[8][2];
    if (MAXP) {
        #pragma unroll
        for (int f = 0; f < 8; f++) { colmax[f][0] = 0.f; colmax[f][1] = 0.f; }
    }
    float zp[2][2] = {{0.f, 0.f}, {0.f, 0.f}};

    const float* gw = GLOB ? &g_gW[(rbase >> 10) * HID] : nullptr;
    #pragma unroll
    for (int mf = 0; mf < 2; mf++) {
        int r0 = rbase + m0 + mf * 16 + gp;
        int r1 = r0 + 8;
        float cc0 = GLOB ? g_c[r0] : 0.f;
        float cc1 = GLOB ? g_c[r1] : 0.f;
        #pragma unroll
        for (int f = 0; f < 8; f++) {
            int c = n0 + f * 8 + 2 * tg;
            float2 bv = *(const float2*)&bias[c];
            float4 a = acc[mf][f];
            float2 o0 = {a.x + bv.x, a.y + bv.y};
            float2 o1 = {a.z + bv.x, a.w + bv.y};
            if (GLOB) {
                float2 gv = *(const float2*)&gw[c];
                o0.x += cc0 * gv.x; o0.y += cc0 * gv.y;
                o1.x += cc1 * gv.x; o1.y += cc1 * gv.y;
            }
            if (RELU) {
                o0.x = fmaxf(o0.x, 0.f); o0.y = fmaxf(o0.y, 0.f);
                o1.x = fmaxf(o1.x, 0.f); o1.y = fmaxf(o1.y, 0.f);
            }
            if (!ZOUT) {
                *(float2*)&Y[(size_t)r0 * 128 + c] = o0;
                *(float2*)&Y[(size_t)r1 * 128 + c] = o1;
            }
            if (MAXP) {
                colmax[f][0] = fmaxf(colmax[f][0], fmaxf(o0.x, o1.x));
                colmax[f][1] = fmaxf(colmax[f][1], fmaxf(o0.y, o1.y));
            }
            if (ZOUT) {
                float w3a = W3[c], w3b = W3[c + 1];
                zp[mf][0] += o0.x * w3a + o0.y * w3b;
                zp[mf][1] += o1.x * w3a + o1.y * w3b;
            }
        }
    }

    if (MAXP) {
        #pragma unroll
        for (int f = 0; f < 8; f++) {
            int c = n0 + f * 8 + 2 * tg;
            atomicMax(&smax[c],     __float_as_int(colmax[f][0]));
            atomicMax(&smax[c + 1], __float_as_int(colmax[f][1]));
        }
        __syncthreads();
        if (tid < 128) g_mpp[(size_t)blockIdx.x * HID + tid] = __int_as_float(smax[tid]);
    }

    if (ZOUT) {
        int slot = ((wid >> 2) << 2) | tg;
        #pragma unroll
        for (int mf = 0; mf < 2; mf++) {
            szp[m0 + mf * 16 + gp][slot]     = zp[mf][0];
            szp[m0 + mf * 16 + gp + 8][slot] = zp[mf][1];
        }
        __syncthreads();
        if (tid < 128) {
            float z = 0.f;
            #pragma unroll
            for (int k = 0; k < 8; k++) z += szp[tid][k];
            g_z[rbase + tid] = z;
        }
    }
}

// ---------------- fused maxpool stage-2 + global path matmuls ----------------
__global__ void k_globs2(const float* __restrict__ Wf, const float* __restrict__ bf,
                         const float* __restrict__ W2) {
    __shared__ float s1[HID];
    __shared__ float s2[HID];
    int g = blockIdx.x, t = threadIdx.x;
    float m = -CUDART_INF_F;
    #pragma unroll
    for (int s = 0; s < 8; s++) m = fmaxf(m, g_mpp[(g * 8 + s) * HID + t]);
    s1[t] = m;
    __syncthreads();
    float acc = bf[t];
    for (int k = 0; k < HID; k++) acc += s1[k] * Wf[k * HID + t];
    s2[t] = acc;
    __syncthreads();
    float a2 = 0.f;
    for (int k = 0; k < HID; k++) a2 += s2[k] * W2[(HID + k) * HID + t];
    g_gW[g * HID + t] = a2;
}

// ---------------- logit aggregation (R3-proven) ----------------
__global__ void k_logit(const float* __restrict__ b3) {
    int node = blockIdx.x * 8 + (threadIdx.x >> 5);
    int lane = threadIdx.x & 31;
    int jb = g_off[node], je = jb + g_deg[node];
    float part = 0.f;
    for (int j = jb + lane; j < je; j += 32)
        part += g_csrnrm[j] * g_z[g_csrsrc[j]];
    #pragma unroll
    for (int o = 16; o; o >>= 1) part += __shfl_xor_sync(0xffffffffu, part, o);
    if (lane == 0) {
        float dv = g_dinv[node];
        g_logit[node] = part + dv * dv * g_z[node] + b3[0];
    }
}

// ---------------- per-graph top-K threshold + mask (R3-proven) ----------------
__global__ void k_topk(float* __restrict__ out) {
    __shared__ float v[NPER];
    __shared__ float wmax[8];
    __shared__ float sth;
    __shared__ int sidx;
    int g = blockIdx.x, t = threadIdx.x;
    int lane = t & 31, warp = t >> 5;
    for (int i = t; i < NPER; i += 256) v[i] = g_logit[g * NPER + i];
    __syncthreads();
    for (int it = 0; it < TOPK; it++) {
        float m = -CUDART_INF_F;
        for (int i = t; i < NPER; i += 256) m = fmaxf(m, v[i]);
        #pragma unroll
        for (int o = 16; o; o >>= 1) m = fmaxf(m, __shfl_xor_sync(0xffffffffu, m, o));
        if (lane == 0) wmax[warp] = m;
        __syncthreads();
        if (t == 0) {
            float mm = wmax[0];
            #pragma unroll
            for (int w = 1; w < 8; w++) mm = fmaxf(mm, wmax[w]);
            sth = mm;
            sidx = 0x7fffffff;
        }
        __syncthreads();
        float mm = sth;
        for (int i = t; i < NPER; i += 256)
            if (v[i] == mm) atomicMin(&sidx, i);
        __syncthreads();
        if (t == 0) v[sidx] = -CUDART_INF_F;
        __syncthreads();
    }
    float th = sth;
    for (int i = t; i < NPER; i += 256)
        out[g * NPER + i] = (g_logit[g * NPER + i] >= th) ? 1.0f : 0.0f;
}

// ---------------- host launcher ----------------
extern "C" void kernel_launch(void* const* d_in, const int* in_sizes, int n_in,
                              void* d_out, int out_size) {
    const float* x    = (const float*)d_in[0];
    const int*   esrc = (const int*)d_in[1];
    const int*   edst = (const int*)d_in[2];
    const float* W0 = (const float*)d_in[4];
    const float* b0 = (const float*)d_in[5];
    const float* W1 = (const float*)d_in[6];
    const float* b1 = (const float*)d_in[7];
    const float* Wf = (const float*)d_in[8];
    const float* bf = (const float*)d_in[9];
    const float* W2 = (const float*)d_in[10];
    const float* b2 = (const float*)d_in[11];
    const float* W3 = (const float*)d_in[12];
    const float* b3 = (const float*)d_in[13];
    float* out = (float*)d_out;

    float *T0, *T1;
    int* degp;
    cudaGetSymbolAddress((void**)&T0, g_T0);
    cudaGetSymbolAddress((void**)&T1, g_T1);
    cudaGetSymbolAddress((void**)&degp, g_deg);

    const int SM64  = (128 * 68 + 64 * 136) * 4;     // 69632
    const int SM128 = (128 * 132 + 128 * 136) * 4;   // 137216
    cudaFuncSetAttribute(k_mgemm<64, true, false, true, false>,
                         cudaFuncAttributeMaxDynamicSharedMemorySize, SM64);
    cudaFuncSetAttribute(k_mgemm<128, true, false, false, false>,
                         cudaFuncAttributeMaxDynamicSharedMemorySize, SM128);
    cudaFuncSetAttribute(k_mgemm<128, true, true, false, true>,
                         cudaFuncAttributeMaxDynamicSharedMemorySize, SM128);

    // --- CSR + norms ---
    cudaMemsetAsync(degp, 0, NNODES * sizeof(int));
    k_hist<<<NEDGES / 256, 256>>>(edst);
    k_scan1<<<256, 256>>>();
    k_scan2<<<1, 256>>>();
    k_scan3<<<256, 256>>>();
    k_fill<<<NEDGES / 256, 256>>>(esrc, edst);

    // --- conv0: h0 = relu(agg(x) @ W0 + b0); epilogue emits maxpool partials ---
    k_agg64<true><<<NNODES / 8, 256>>>(x, T1);
    k_mgemm<64, true, false, true, false><<<NNODES / 128, 256, SM64>>>(T1, W0, b0, T0, nullptr);

    // --- global path: mp2 + (mp @ Wf + bf) @ W2_bottom ---
    k_globs2<<<NGRAPH, HID>>>(Wf, bf, W2);

    // --- conv1 (applied twice with same weights) ---
    k_agg128<<<NNODES / 8, 256>>>(T0, T1);
    k_mgemm<128, true, false, false, false><<<NNODES / 128, 256, SM128>>>(T1, W1, b1, T0, nullptr);
    k_agg128<<<NNODES / 8, 256>>>(T0, T1);
    k_mgemm<128, true, false, false, false><<<NNODES / 128, 256, SM128>>>(T1, W1, b1, T0, nullptr);

    // --- conv2 + conv3 projection fused: epilogue computes z = h . W3, no h store ---
    k_agg128<<<NNODES / 8, 256>>>(T0, T1);
    k_mgemm<128, true, true, false, true><<<NNODES / 128, 256, SM128>>>(T1, W2, b2, nullptr, W3);

    // --- logit = agg(z) + b3, then per-graph top-10 mask ---
    k_logit<<<NNODES / 8, 256>>>(b3);
    k_topk<<<NGRAPH, 256>>>(out);
}